// round 15
// baseline (speedup 1.0000x reference)
#include <cuda_runtime.h>

#define BB 16
#define CC 512
#define NN 4096
#define HH 512
#define NSPLIT 32

// ---------------- scratch (device globals: no allocation allowed) ----------
// All accumulators are zero at module load and re-zeroed at the TAIL of each
// launch (in k_softmax, after their last use) — no k_zero kernel needed.
__device__ float g_s[BB * NN];    // s[b,n]  = sum_c x
__device__ float g_t[BB * CC];    // t[b,c]  = sum_n x
__device__ float g_u[BB * HH];    // u[b,h]  = sum_n s * w_cf
__device__ float g_p[BB * HH];    // p[b,h]  = sum_c t * w_sf
__device__ float g_v[BB * NN];    // v[b,n]  = sum_h u * w_cg   (overwritten)
__device__ float g_q[BB * CC];    // q[b,c]  = sum_h p * w_sg   (overwritten)
__device__ float g_vp[NSPLIT * BB * NN];  // v partials (overwritten)
__device__ float g_qp[NSPLIT * BB * CC];  // q partials (overwritten)
__device__ float g_chc[BB * CC];  // ch_comp (accumulated; tail-zeroed)
__device__ float g_spc[BB * NN];  // sp_comp (accumulated; tail-zeroed)
__device__ float g_cm[BB * CC];   // channel mask (overwritten)
__device__ float g_sm[BB * NN];   // spatial mask (overwritten)

__device__ __forceinline__ float warp_sum(float v) {
    v += __shfl_down_sync(0xFFFFFFFFu, v, 16);
    v += __shfl_down_sync(0xFFFFFFFFu, v, 8);
    v += __shfl_down_sync(0xFFFFFFFFu, v, 4);
    v += __shfl_down_sync(0xFFFFFFFFu, v, 2);
    v += __shfl_down_sync(0xFFFFFFFFu, v, 1);
    return v;
}

// ---------------- K1: fused row/col sums, one pass over x -----------------
// grid (4, 8, B), block 256. Streaming loads of x (no L2 pollution).
__global__ void k_sums(const float* __restrict__ x) {
    const int b = blockIdx.z;
    const int n0 = blockIdx.x * 1024;
    const int c0 = blockIdx.y * 64;
    const int tid = threadIdx.x;
    const int lane = tid & 31, wid = tid >> 5;
    __shared__ float tp[64][9];

    const float4* xp = reinterpret_cast<const float4*>(x + (size_t)b * CC * NN + n0) + tid;
    float4 s4 = make_float4(0.f, 0.f, 0.f, 0.f);

    for (int c = 0; c < 64; c += 4) {
        float4 a0 = __ldcs(xp + (size_t)(c0 + c + 0) * (NN / 4));
        float4 a1 = __ldcs(xp + (size_t)(c0 + c + 1) * (NN / 4));
        float4 a2 = __ldcs(xp + (size_t)(c0 + c + 2) * (NN / 4));
        float4 a3 = __ldcs(xp + (size_t)(c0 + c + 3) * (NN / 4));
        s4.x += a0.x + a1.x + a2.x + a3.x;
        s4.y += a0.y + a1.y + a2.y + a3.y;
        s4.z += a0.z + a1.z + a2.z + a3.z;
        s4.w += a0.w + a1.w + a2.w + a3.w;
        float r0 = warp_sum(a0.x + a0.y + a0.z + a0.w);
        float r1 = warp_sum(a1.x + a1.y + a1.z + a1.w);
        float r2 = warp_sum(a2.x + a2.y + a2.z + a2.w);
        float r3 = warp_sum(a3.x + a3.y + a3.z + a3.w);
        if (lane == 0) {
            tp[c + 0][wid] = r0;
            tp[c + 1][wid] = r1;
            tp[c + 2][wid] = r2;
            tp[c + 3][wid] = r3;
        }
    }
    __syncthreads();
    if (tid < 64) {
        float t = tp[tid][0] + tp[tid][1] + tp[tid][2] + tp[tid][3] +
                  tp[tid][4] + tp[tid][5] + tp[tid][6] + tp[tid][7];
        atomicAdd(&g_t[b * CC + c0 + tid], t);
    }
    float* sdst = g_s + (size_t)b * NN + n0 + tid * 4;
    atomicAdd(sdst + 0, s4.x);
    atomicAdd(sdst + 1, s4.y);
    atomicAdd(sdst + 2, s4.z);
    atomicAdd(sdst + 3, s4.w);
}

// ---------------- K2a: out[b,h] = sum_k in[b,k] * W[h,k] ------------------
__global__ void k_gemmA(const float* __restrict__ w_cf, const float* __restrict__ w_sf) {
    const int z = blockIdx.z;
    const float* in = z ? g_t : g_s;
    const float* W = z ? w_sf : w_cf;
    float* out = z ? g_p : g_u;
    const int K = z ? CC : NN;
    const int h0 = blockIdx.x * 16;
    const int kper = K >> 3;
    const int k0 = blockIdx.y * kper;
    const int tid = threadIdx.x;
    const int bb = tid & 15, hh = tid >> 4;
    __shared__ float in_s[16][65];
    __shared__ float w_s[16][65];

    float acc = 0.f;
    for (int kc = 0; kc < kper; kc += 64) {
        for (int t = tid; t < 1024; t += 256) {
            int r = t >> 6, k = t & 63;
            in_s[r][k] = in[(size_t)r * K + k0 + kc + k];
            w_s[r][k] = W[(size_t)(h0 + r) * K + k0 + kc + k];
        }
        __syncthreads();
#pragma unroll
        for (int k = 0; k < 64; k++) acc += in_s[bb][k] * w_s[hh][k];
        __syncthreads();
    }
    atomicAdd(&out[bb * HH + h0 + hh], acc);
}

// ---------------- K2b: partial out[b,m] = sum_{h in split} in[b,h]*W[h,m] -
// grid (4, NSPLIT, 4), block 256. Plain STG.128 partials, no atomics.
__global__ void k_gB(const float* __restrict__ w_cg, const float* __restrict__ w_sg) {
    const int gemm = blockIdx.z >> 1;
    const int b0 = (blockIdx.z & 1) * 8;
    const int split = blockIdx.y;
    const int h0 = split * 16;
    const float* in = gemm ? g_p : g_u;
    const float* W = gemm ? w_sg : w_cg;
    float* outp = gemm ? g_qp : g_vp;
    const int M = gemm ? CC : NN;
    const int tid = threadIdx.x;
    const int m4 = blockIdx.x * 256 + tid;  // float4 column index

    __shared__ float in_s[8][17];
    if (tid < 128) {
        int b = tid >> 4, h = tid & 15;
        in_s[b][h] = in[(b0 + b) * HH + h0 + h];
    }
    __syncthreads();
    if (m4 * 4 >= M) return;

    const float4* Wv = reinterpret_cast<const float4*>(W);
    float4 acc[8];
#pragma unroll
    for (int b = 0; b < 8; b++) acc[b] = make_float4(0.f, 0.f, 0.f, 0.f);

#pragma unroll
    for (int h = 0; h < 16; h++) {
        float4 w4 = __ldcs(Wv + (size_t)(h0 + h) * (M / 4) + m4);
#pragma unroll
        for (int b = 0; b < 8; b++) {
            float s = in_s[b][h];
            acc[b].x += s * w4.x;
            acc[b].y += s * w4.y;
            acc[b].z += s * w4.z;
            acc[b].w += s * w4.w;
        }
    }
    float4* op = reinterpret_cast<float4*>(outp) + (size_t)split * (BB * M / 4);
#pragma unroll
    for (int b = 0; b < 8; b++) op[(b0 + b) * (M / 4) + m4] = acc[b];
}

// ---------------- K2c: fold the NSPLIT partials into g_v / g_q -------------
__global__ void k_red() {
    const int NV4 = BB * NN / 4;  // 16384
    const int NQ4 = BB * CC / 4;  // 2048
    int idx = blockIdx.x * 256 + threadIdx.x;
    if (idx < NV4) {
        const float4* vp = reinterpret_cast<const float4*>(g_vp);
        float4 a = make_float4(0.f, 0.f, 0.f, 0.f);
#pragma unroll
        for (int s2 = 0; s2 < NSPLIT; s2++) {
            float4 t = vp[(size_t)s2 * NV4 + idx];
            a.x += t.x; a.y += t.y; a.z += t.z; a.w += t.w;
        }
        reinterpret_cast<float4*>(g_v)[idx] = a;
    } else if (idx < NV4 + NQ4) {
        int j = idx - NV4;
        const float4* qp = reinterpret_cast<const float4*>(g_qp);
        float4 a = make_float4(0.f, 0.f, 0.f, 0.f);
#pragma unroll
        for (int s2 = 0; s2 < NSPLIT; s2++) {
            float4 t = qp[(size_t)s2 * NQ4 + j];
            a.x += t.x; a.y += t.y; a.z += t.z; a.w += t.w;
        }
        reinterpret_cast<float4*>(g_q)[j] = a;
    }
}

// ---------------- K3: fused comps, one pass over x ------------------------
__global__ void k_comps(const float* __restrict__ x) {
    const int b = blockIdx.z;
    const int n0 = blockIdx.x * 1024;
    const int c0 = blockIdx.y * 64;
    const int tid = threadIdx.x;
    const int lane = tid & 31, wid = tid >> 5;
    __shared__ float tp[64][9];

    const float4* xp = reinterpret_cast<const float4*>(x + (size_t)b * CC * NN + n0) + tid;
    const float4 vw = *reinterpret_cast<const float4*>(g_v + (size_t)b * NN + n0 + tid * 4);
    float4 sp4 = make_float4(0.f, 0.f, 0.f, 0.f);

    for (int c = 0; c < 64; c += 4) {
        float q0 = g_q[b * CC + c0 + c + 0];
        float q1 = g_q[b * CC + c0 + c + 1];
        float q2 = g_q[b * CC + c0 + c + 2];
        float q3 = g_q[b * CC + c0 + c + 3];
        float4 a0 = __ldcs(xp + (size_t)(c0 + c + 0) * (NN / 4));
        float4 a1 = __ldcs(xp + (size_t)(c0 + c + 1) * (NN / 4));
        float4 a2 = __ldcs(xp + (size_t)(c0 + c + 2) * (NN / 4));
        float4 a3 = __ldcs(xp + (size_t)(c0 + c + 3) * (NN / 4));
        sp4.x += a0.x * q0 + a1.x * q1 + a2.x * q2 + a3.x * q3;
        sp4.y += a0.y * q0 + a1.y * q1 + a2.y * q2 + a3.y * q3;
        sp4.z += a0.z * q0 + a1.z * q1 + a2.z * q2 + a3.z * q3;
        sp4.w += a0.w * q0 + a1.w * q1 + a2.w * q2 + a3.w * q3;
        float r0 = warp_sum(a0.x * vw.x + a0.y * vw.y + a0.z * vw.z + a0.w * vw.w);
        float r1 = warp_sum(a1.x * vw.x + a1.y * vw.y + a1.z * vw.z + a1.w * vw.w);
        float r2 = warp_sum(a2.x * vw.x + a2.y * vw.y + a2.z * vw.z + a2.w * vw.w);
        float r3 = warp_sum(a3.x * vw.x + a3.y * vw.y + a3.z * vw.z + a3.w * vw.w);
        if (lane == 0) {
            tp[c + 0][wid] = r0;
            tp[c + 1][wid] = r1;
            tp[c + 2][wid] = r2;
            tp[c + 3][wid] = r3;
        }
    }
    __syncthreads();
    if (tid < 64) {
        float t = tp[tid][0] + tp[tid][1] + tp[tid][2] + tp[tid][3] +
                  tp[tid][4] + tp[tid][5] + tp[tid][6] + tp[tid][7];
        atomicAdd(&g_chc[b * CC + c0 + tid], t);
    }
    float* sdst = g_spc + (size_t)b * NN + n0 + tid * 4;
    atomicAdd(sdst + 0, sp4.x);
    atomicAdd(sdst + 1, sp4.y);
    atomicAdd(sdst + 2, sp4.z);
    atomicAdd(sdst + 3, sp4.w);
}

// ---------------- K4: softmaxes; writes masks; tail-zeroes accumulators ---
// grid (2, B): x=0 -> channel softmax (len C), x=1 -> spatial (len N).
// After the final write, each thread zeroes exactly the src indices it read
// (g_chc/g_spc), and the 32 blocks cooperatively zero the dead accumulators
// g_s/g_t/g_u/g_p so the next graph replay starts from a clean state.
__global__ void k_softmax(float* out_cm, float* out_sm) {
    const int b = blockIdx.y;
    const int len = blockIdx.x ? NN : CC;
    const float* src = blockIdx.x ? (g_spc + b * NN) : (g_chc + b * CC);
    float* srcw = blockIdx.x ? (g_spc + b * NN) : (g_chc + b * CC);
    float* dst = blockIdx.x ? (g_sm + b * NN) : (g_cm + b * CC);
    float* dst2 = blockIdx.x ? (out_sm ? out_sm + b * NN : nullptr)
                             : (out_cm ? out_cm + b * CC : nullptr);
    const int tid = threadIdx.x;
    const int lane = tid & 31, wid = tid >> 5;
    __shared__ float red[8];

    float m = -1e30f;
    for (int i = tid; i < len; i += 256) m = fmaxf(m, src[i]);
    m = fmaxf(m, __shfl_xor_sync(0xFFFFFFFFu, m, 16));
    m = fmaxf(m, __shfl_xor_sync(0xFFFFFFFFu, m, 8));
    m = fmaxf(m, __shfl_xor_sync(0xFFFFFFFFu, m, 4));
    m = fmaxf(m, __shfl_xor_sync(0xFFFFFFFFu, m, 2));
    m = fmaxf(m, __shfl_xor_sync(0xFFFFFFFFu, m, 1));
    if (lane == 0) red[wid] = m;
    __syncthreads();
    float m_all = red[0];
#pragma unroll
    for (int w = 1; w < 8; w++) m_all = fmaxf(m_all, red[w]);
    __syncthreads();

    float s = 0.f;
    for (int i = tid; i < len; i += 256) s += __expf(src[i] - m_all);
    s = warp_sum(s);
    if (lane == 0) red[wid] = s;
    __syncthreads();
    float tot = red[0] + red[1] + red[2] + red[3] + red[4] + red[5] + red[6] + red[7];
    float inv = 1.f / tot;

    for (int i = tid; i < len; i += 256) {
        float e = __expf(src[i] - m_all) * inv;
        dst[i] = e;
        if (dst2) dst2[i] = e;
        srcw[i] = 0.f;  // reset comp accumulator for next replay
    }

    // Zero the dead accumulators (last consumers ran earlier in the stream).
    const int gb = b * 2 + blockIdx.x;           // 0..31
    const int base = gb * 256 + tid;             // stride 8192 covers arrays
#pragma unroll
    for (int i = base; i < BB * NN; i += 32 * 256) g_s[i] = 0.f;
    if (base < BB * CC) {                        // BB*CC == 8192 exactly
        g_t[base] = 0.f;
        g_u[base] = 0.f;
        g_p[base] = 0.f;
    }
}

// ---------------- K5: outputs = x * cm[b,c] * sm[b,n] ---------------------
// Streaming x read + streaming out write; masks stay L2-resident.
__global__ void k_final(const float* __restrict__ x, float* __restrict__ out) {
    const int idx = blockIdx.x * 256 + threadIdx.x;  // float4 index
    const int n4 = idx & (NN / 4 - 1);
    const int c = (idx >> 10) & (CC - 1);
    const int b = idx >> 19;
    const float cm = g_cm[b * CC + c];
    const float4 sm = reinterpret_cast<const float4*>(g_sm)[b * (NN / 4) + n4];
    const float4 xv = __ldcs(reinterpret_cast<const float4*>(x) + idx);
    float4 o;
    o.x = xv.x * cm * sm.x;
    o.y = xv.y * cm * sm.y;
    o.z = xv.z * cm * sm.z;
    o.w = xv.w * cm * sm.w;
    __stcs(reinterpret_cast<float4*>(out) + idx, o);
}

// ---------------- launch ---------------------------------------------------
extern "C" void kernel_launch(void* const* d_in, const int* in_sizes, int n_in,
                              void* d_out, int out_size) {
    const float* x = (const float*)d_in[0];
    const float* w_cf = (const float*)d_in[1];
    const float* w_cg = (const float*)d_in[2];
    const float* w_sf = (const float*)d_in[3];
    const float* w_sg = (const float*)d_in[4];
    float* out = (float*)d_out;

    const long long n_out_main = (long long)BB * CC * NN;
    const long long n_full = n_out_main + (long long)BB * CC + (long long)BB * NN;
    float* out_cm = nullptr;
    float* out_sm = nullptr;
    if ((long long)out_size >= n_full) {
        out_cm = out + (size_t)n_out_main;
        out_sm = out_cm + BB * CC;
    }

    k_sums<<<dim3(4, 8, BB), 256>>>(x);
    k_gemmA<<<dim3(32, 8, 2), 256>>>(w_cf, w_sf);
    k_gB<<<dim3(4, NSPLIT, 4), 256>>>(w_cg, w_sg);
    k_red<<<72, 256>>>();
    k_comps<<<dim3(4, 8, BB), 256>>>(x);
    k_softmax<<<dim3(2, BB), 256>>>(out_cm, out_sm);
    k_final<<<32768, 256>>>(x, out);
}

// round 16
// speedup vs baseline: 1.0139x; 1.0139x over previous
#include <cuda_runtime.h>

#define BB 16
#define CC 512
#define NN 4096
#define HH 512
#define NSPLIT 32

// ---------------- scratch (device globals: no allocation allowed) ----------
// All accumulators are zero at module load and re-zeroed at the TAIL of each
// launch (in k_softmax, after their last use) — no k_zero kernel needed.
__device__ float g_s[BB * NN];    // s[b,n]  = sum_c x          (tail-zeroed)
__device__ float g_t[BB * CC];    // t[b,c]  = sum_n x          (tail-zeroed)
__device__ float g_u[BB * HH];    // u[b,h]                      (tail-zeroed)
__device__ float g_p[BB * HH];    // p[b,h]                      (tail-zeroed)
__device__ float g_v[BB * NN];    // v[b,n]  (atomic-accumulated; tail-zeroed)
__device__ float g_q[BB * CC];    // q[b,c]  (atomic-accumulated; tail-zeroed)
__device__ float g_vp[NSPLIT * BB * NN];  // v partials (overwritten)
__device__ float g_qp[NSPLIT * BB * CC];  // q partials (overwritten)
__device__ float g_chc[BB * CC];  // ch_comp (accumulated; tail-zeroed)
__device__ float g_spc[BB * NN];  // sp_comp (accumulated; tail-zeroed)
__device__ float g_cm[BB * CC];   // channel mask (overwritten)
__device__ float g_sm[BB * NN];   // spatial mask (overwritten)

__device__ __forceinline__ float warp_sum(float v) {
    v += __shfl_down_sync(0xFFFFFFFFu, v, 16);
    v += __shfl_down_sync(0xFFFFFFFFu, v, 8);
    v += __shfl_down_sync(0xFFFFFFFFu, v, 4);
    v += __shfl_down_sync(0xFFFFFFFFu, v, 2);
    v += __shfl_down_sync(0xFFFFFFFFu, v, 1);
    return v;
}

// ---------------- K1: fused row/col sums, one pass over x -----------------
// grid (4, 8, B), block 256. Streaming loads of x (no L2 pollution).
__global__ void k_sums(const float* __restrict__ x) {
    const int b = blockIdx.z;
    const int n0 = blockIdx.x * 1024;
    const int c0 = blockIdx.y * 64;
    const int tid = threadIdx.x;
    const int lane = tid & 31, wid = tid >> 5;
    __shared__ float tp[64][9];

    const float4* xp = reinterpret_cast<const float4*>(x + (size_t)b * CC * NN + n0) + tid;
    float4 s4 = make_float4(0.f, 0.f, 0.f, 0.f);

    for (int c = 0; c < 64; c += 4) {
        float4 a0 = __ldcs(xp + (size_t)(c0 + c + 0) * (NN / 4));
        float4 a1 = __ldcs(xp + (size_t)(c0 + c + 1) * (NN / 4));
        float4 a2 = __ldcs(xp + (size_t)(c0 + c + 2) * (NN / 4));
        float4 a3 = __ldcs(xp + (size_t)(c0 + c + 3) * (NN / 4));
        s4.x += a0.x + a1.x + a2.x + a3.x;
        s4.y += a0.y + a1.y + a2.y + a3.y;
        s4.z += a0.z + a1.z + a2.z + a3.z;
        s4.w += a0.w + a1.w + a2.w + a3.w;
        float r0 = warp_sum(a0.x + a0.y + a0.z + a0.w);
        float r1 = warp_sum(a1.x + a1.y + a1.z + a1.w);
        float r2 = warp_sum(a2.x + a2.y + a2.z + a2.w);
        float r3 = warp_sum(a3.x + a3.y + a3.z + a3.w);
        if (lane == 0) {
            tp[c + 0][wid] = r0;
            tp[c + 1][wid] = r1;
            tp[c + 2][wid] = r2;
            tp[c + 3][wid] = r3;
        }
    }
    __syncthreads();
    if (tid < 64) {
        float t = tp[tid][0] + tp[tid][1] + tp[tid][2] + tp[tid][3] +
                  tp[tid][4] + tp[tid][5] + tp[tid][6] + tp[tid][7];
        atomicAdd(&g_t[b * CC + c0 + tid], t);
    }
    float* sdst = g_s + (size_t)b * NN + n0 + tid * 4;
    atomicAdd(sdst + 0, s4.x);
    atomicAdd(sdst + 1, s4.y);
    atomicAdd(sdst + 2, s4.z);
    atomicAdd(sdst + 3, s4.w);
}

// ---------------- K2a: out[b,h] = sum_k in[b,k] * W[h,k] ------------------
__global__ void k_gemmA(const float* __restrict__ w_cf, const float* __restrict__ w_sf) {
    const int z = blockIdx.z;
    const float* in = z ? g_t : g_s;
    const float* W = z ? w_sf : w_cf;
    float* out = z ? g_p : g_u;
    const int K = z ? CC : NN;
    const int h0 = blockIdx.x * 16;
    const int kper = K >> 3;
    const int k0 = blockIdx.y * kper;
    const int tid = threadIdx.x;
    const int bb = tid & 15, hh = tid >> 4;
    __shared__ float in_s[16][65];
    __shared__ float w_s[16][65];

    float acc = 0.f;
    for (int kc = 0; kc < kper; kc += 64) {
        for (int t = tid; t < 1024; t += 256) {
            int r = t >> 6, k = t & 63;
            in_s[r][k] = in[(size_t)r * K + k0 + kc + k];
            w_s[r][k] = W[(size_t)(h0 + r) * K + k0 + kc + k];
        }
        __syncthreads();
#pragma unroll
        for (int k = 0; k < 64; k++) acc += in_s[bb][k] * w_s[hh][k];
        __syncthreads();
    }
    atomicAdd(&out[bb * HH + h0 + hh], acc);
}

// ---------------- K2b: partial out[b,m] = sum_{h in split} in[b,h]*W[h,m] -
// grid (4, NSPLIT, 4), block 256. Plain STG.128 partials, no atomics.
__global__ void k_gB(const float* __restrict__ w_cg, const float* __restrict__ w_sg) {
    const int gemm = blockIdx.z >> 1;
    const int b0 = (blockIdx.z & 1) * 8;
    const int split = blockIdx.y;
    const int h0 = split * 16;
    const float* in = gemm ? g_p : g_u;
    const float* W = gemm ? w_sg : w_cg;
    float* outp = gemm ? g_qp : g_vp;
    const int M = gemm ? CC : NN;
    const int tid = threadIdx.x;
    const int m4 = blockIdx.x * 256 + tid;  // float4 column index

    __shared__ float in_s[8][17];
    if (tid < 128) {
        int b = tid >> 4, h = tid & 15;
        in_s[b][h] = in[(b0 + b) * HH + h0 + h];
    }
    __syncthreads();
    if (m4 * 4 >= M) return;

    const float4* Wv = reinterpret_cast<const float4*>(W);
    float4 acc[8];
#pragma unroll
    for (int b = 0; b < 8; b++) acc[b] = make_float4(0.f, 0.f, 0.f, 0.f);

#pragma unroll
    for (int h = 0; h < 16; h++) {
        float4 w4 = __ldcs(Wv + (size_t)(h0 + h) * (M / 4) + m4);
#pragma unroll
        for (int b = 0; b < 8; b++) {
            float s = in_s[b][h];
            acc[b].x += s * w4.x;
            acc[b].y += s * w4.y;
            acc[b].z += s * w4.z;
            acc[b].w += s * w4.w;
        }
    }
    float4* op = reinterpret_cast<float4*>(outp) + (size_t)split * (BB * M / 4);
#pragma unroll
    for (int b = 0; b < 8; b++) op[(b0 + b) * (M / 4) + m4] = acc[b];
}

// ---------------- K2c: fold partials into g_v / g_q (4-way parallel) ------
// grid (72, 4), block 256. blockIdx.y = group of 8 splits; atomicAdd results.
// g_v/g_q start zeroed (module load / k_softmax tail).
__global__ void k_red() {
    const int NV4 = BB * NN / 4;  // 16384
    const int NQ4 = BB * CC / 4;  // 2048
    const int s0 = blockIdx.y * 8;
    int idx = blockIdx.x * 256 + threadIdx.x;
    if (idx < NV4) {
        const float4* vp = reinterpret_cast<const float4*>(g_vp) + (size_t)s0 * NV4 + idx;
        float4 a = make_float4(0.f, 0.f, 0.f, 0.f);
#pragma unroll
        for (int s2 = 0; s2 < 8; s2++) {
            float4 t = vp[(size_t)s2 * NV4];
            a.x += t.x; a.y += t.y; a.z += t.z; a.w += t.w;
        }
        float* dst = g_v + idx * 4;
        atomicAdd(dst + 0, a.x);
        atomicAdd(dst + 1, a.y);
        atomicAdd(dst + 2, a.z);
        atomicAdd(dst + 3, a.w);
    } else if (idx < NV4 + NQ4) {
        int j = idx - NV4;
        const float4* qp = reinterpret_cast<const float4*>(g_qp) + (size_t)s0 * NQ4 + j;
        float4 a = make_float4(0.f, 0.f, 0.f, 0.f);
#pragma unroll
        for (int s2 = 0; s2 < 8; s2++) {
            float4 t = qp[(size_t)s2 * NQ4];
            a.x += t.x; a.y += t.y; a.z += t.z; a.w += t.w;
        }
        float* dst = g_q + j * 4;
        atomicAdd(dst + 0, a.x);
        atomicAdd(dst + 1, a.y);
        atomicAdd(dst + 2, a.z);
        atomicAdd(dst + 3, a.w);
    }
}

// ---------------- K3: fused comps, one pass over x ------------------------
__global__ void k_comps(const float* __restrict__ x) {
    const int b = blockIdx.z;
    const int n0 = blockIdx.x * 1024;
    const int c0 = blockIdx.y * 64;
    const int tid = threadIdx.x;
    const int lane = tid & 31, wid = tid >> 5;
    __shared__ float tp[64][9];

    const float4* xp = reinterpret_cast<const float4*>(x + (size_t)b * CC * NN + n0) + tid;
    const float4 vw = *reinterpret_cast<const float4*>(g_v + (size_t)b * NN + n0 + tid * 4);
    float4 sp4 = make_float4(0.f, 0.f, 0.f, 0.f);

    for (int c = 0; c < 64; c += 4) {
        float q0 = g_q[b * CC + c0 + c + 0];
        float q1 = g_q[b * CC + c0 + c + 1];
        float q2 = g_q[b * CC + c0 + c + 2];
        float q3 = g_q[b * CC + c0 + c + 3];
        float4 a0 = __ldcs(xp + (size_t)(c0 + c + 0) * (NN / 4));
        float4 a1 = __ldcs(xp + (size_t)(c0 + c + 1) * (NN / 4));
        float4 a2 = __ldcs(xp + (size_t)(c0 + c + 2) * (NN / 4));
        float4 a3 = __ldcs(xp + (size_t)(c0 + c + 3) * (NN / 4));
        sp4.x += a0.x * q0 + a1.x * q1 + a2.x * q2 + a3.x * q3;
        sp4.y += a0.y * q0 + a1.y * q1 + a2.y * q2 + a3.y * q3;
        sp4.z += a0.z * q0 + a1.z * q1 + a2.z * q2 + a3.z * q3;
        sp4.w += a0.w * q0 + a1.w * q1 + a2.w * q2 + a3.w * q3;
        float r0 = warp_sum(a0.x * vw.x + a0.y * vw.y + a0.z * vw.z + a0.w * vw.w);
        float r1 = warp_sum(a1.x * vw.x + a1.y * vw.y + a1.z * vw.z + a1.w * vw.w);
        float r2 = warp_sum(a2.x * vw.x + a2.y * vw.y + a2.z * vw.z + a2.w * vw.w);
        float r3 = warp_sum(a3.x * vw.x + a3.y * vw.y + a3.z * vw.z + a3.w * vw.w);
        if (lane == 0) {
            tp[c + 0][wid] = r0;
            tp[c + 1][wid] = r1;
            tp[c + 2][wid] = r2;
            tp[c + 3][wid] = r3;
        }
    }
    __syncthreads();
    if (tid < 64) {
        float t = tp[tid][0] + tp[tid][1] + tp[tid][2] + tp[tid][3] +
                  tp[tid][4] + tp[tid][5] + tp[tid][6] + tp[tid][7];
        atomicAdd(&g_chc[b * CC + c0 + tid], t);
    }
    float* sdst = g_spc + (size_t)b * NN + n0 + tid * 4;
    atomicAdd(sdst + 0, sp4.x);
    atomicAdd(sdst + 1, sp4.y);
    atomicAdd(sdst + 2, sp4.z);
    atomicAdd(sdst + 3, sp4.w);
}

// ---------------- K4: softmaxes; writes masks; tail-zeroes accumulators ---
// grid (2, B). After the final write, zero all accumulators (g_chc/g_spc per
// thread-read-index; g_s/g_t/g_u/g_p/g_v/g_q cooperatively) for next replay.
__global__ void k_softmax(float* out_cm, float* out_sm) {
    const int b = blockIdx.y;
    const int len = blockIdx.x ? NN : CC;
    const float* src = blockIdx.x ? (g_spc + b * NN) : (g_chc + b * CC);
    float* srcw = blockIdx.x ? (g_spc + b * NN) : (g_chc + b * CC);
    float* dst = blockIdx.x ? (g_sm + b * NN) : (g_cm + b * CC);
    float* dst2 = blockIdx.x ? (out_sm ? out_sm + b * NN : nullptr)
                             : (out_cm ? out_cm + b * CC : nullptr);
    const int tid = threadIdx.x;
    const int lane = tid & 31, wid = tid >> 5;
    __shared__ float red[8];

    float m = -1e30f;
    for (int i = tid; i < len; i += 256) m = fmaxf(m, src[i]);
    m = fmaxf(m, __shfl_xor_sync(0xFFFFFFFFu, m, 16));
    m = fmaxf(m, __shfl_xor_sync(0xFFFFFFFFu, m, 8));
    m = fmaxf(m, __shfl_xor_sync(0xFFFFFFFFu, m, 4));
    m = fmaxf(m, __shfl_xor_sync(0xFFFFFFFFu, m, 2));
    m = fmaxf(m, __shfl_xor_sync(0xFFFFFFFFu, m, 1));
    if (lane == 0) red[wid] = m;
    __syncthreads();
    float m_all = red[0];
#pragma unroll
    for (int w = 1; w < 8; w++) m_all = fmaxf(m_all, red[w]);
    __syncthreads();

    float s = 0.f;
    for (int i = tid; i < len; i += 256) s += __expf(src[i] - m_all);
    s = warp_sum(s);
    if (lane == 0) red[wid] = s;
    __syncthreads();
    float tot = red[0] + red[1] + red[2] + red[3] + red[4] + red[5] + red[6] + red[7];
    float inv = 1.f / tot;

    for (int i = tid; i < len; i += 256) {
        float e = __expf(src[i] - m_all) * inv;
        dst[i] = e;
        if (dst2) dst2[i] = e;
        srcw[i] = 0.f;  // reset comp accumulator for next replay
    }

    // Zero dead accumulators (all consumers ran earlier in the stream).
    const int gb = b * 2 + blockIdx.x;           // 0..31
    const int base = gb * 256 + tid;             // 0..8191
#pragma unroll
    for (int i = base; i < BB * NN; i += 32 * 256) {
        g_s[i] = 0.f;
        g_v[i] = 0.f;
    }
    if (base < BB * CC) {                        // BB*CC == 8192 exactly
        g_t[base] = 0.f;
        g_u[base] = 0.f;
        g_p[base] = 0.f;
        g_q[base] = 0.f;
    }
}

// ---------------- K5: outputs = x * cm[b,c] * sm[b,n] ---------------------
// Streaming x read + streaming out write; masks stay L2-resident.
__global__ void k_final(const float* __restrict__ x, float* __restrict__ out) {
    const int idx = blockIdx.x * 256 + threadIdx.x;  // float4 index
    const int n4 = idx & (NN / 4 - 1);
    const int c = (idx >> 10) & (CC - 1);
    const int b = idx >> 19;
    const float cm = g_cm[b * CC + c];
    const float4 sm = reinterpret_cast<const float4*>(g_sm)[b * (NN / 4) + n4];
    const float4 xv = __ldcs(reinterpret_cast<const float4*>(x) + idx);
    float4 o;
    o.x = xv.x * cm * sm.x;
    o.y = xv.y * cm * sm.y;
    o.z = xv.z * cm * sm.z;
    o.w = xv.w * cm * sm.w;
    __stcs(reinterpret_cast<float4*>(out) + idx, o);
}

// ---------------- launch ---------------------------------------------------
extern "C" void kernel_launch(void* const* d_in, const int* in_sizes, int n_in,
                              void* d_out, int out_size) {
    const float* x = (const float*)d_in[0];
    const float* w_cf = (const float*)d_in[1];
    const float* w_cg = (const float*)d_in[2];
    const float* w_sf = (const float*)d_in[3];
    const float* w_sg = (const float*)d_in[4];
    float* out = (float*)d_out;

    const long long n_out_main = (long long)BB * CC * NN;
    const long long n_full = n_out_main + (long long)BB * CC + (long long)BB * NN;
    float* out_cm = nullptr;
    float* out_sm = nullptr;
    if ((long long)out_size >= n_full) {
        out_cm = out + (size_t)n_out_main;
        out_sm = out_cm + BB * CC;
    }

    k_sums<<<dim3(4, 8, BB), 256>>>(x);
    k_gemmA<<<dim3(32, 8, 2), 256>>>(w_cf, w_sf);
    k_gB<<<dim3(4, NSPLIT, 4), 256>>>(w_cg, w_sg);
    k_red<<<dim3(72, 4), 256>>>();
    k_comps<<<dim3(4, 8, BB), 256>>>(x);
    k_softmax<<<dim3(2, BB), 256>>>(out_cm, out_sm);
    k_final<<<32768, 256>>>(x, out);
}